// round 10
// baseline (speedup 1.0000x reference)
#include <cuda_runtime.h>

#define NCOLS     16384
#define NROWS_MAX 4096
#define KSEL      655u
#define CAP       2560u          // candidate capacity per row
#define BCAP      512u           // boundary-bin buffer capacity

// fkey(1.0f) = 0x3F800000 | 0x80000000 = 0xBF800000 (low 15 bits zero: bin-aligned)
#define KMIN 0xBF800000u
// for ANY float v:  (v >= 1.0f)  <=>  (fkey(v) >= KMIN)
#define FTHR 1.0f

__device__ float    g_boost[NCOLS];
__device__ unsigned g_cand[(size_t)NROWS_MAX * CAP];   // packed: (key & 0xFFFFC000) | idx14
__device__ unsigned g_count[NROWS_MAX];

__global__ void boost_kernel(const float* __restrict__ duty) {
    int i = blockIdx.x * blockDim.x + threadIdx.x;
    if (i < NCOLS) {
        const float target = 655.0f / 16384.0f;   // exact in f32
        float d = target - duty[i];               // same f32 op as reference
        g_boost[i] = (float)exp((double)d);       // correctly-rounded f32 exp
    }
}

// monotonic float->uint transform: order(key) == order(float)
__device__ __forceinline__ unsigned fkey(float f) {
    unsigned u = __float_as_uint(f);
    return u ^ (((unsigned)((int)u >> 31)) | 0x80000000u);
}

// fkey for values known positive (candidates are >= FTHR > 0)
__device__ __forceinline__ unsigned fkey_pos(float f) {
    return __float_as_uint(f) | 0x80000000u;
}

__device__ __forceinline__ uint4 keys4_at(const float4* __restrict__ xin,
                                          const float4* __restrict__ bfv, int i4) {
    float4 xv = __ldg(&xin[i4]);
    float4 bv = __ldg(&bfv[i4]);
    uint4 k;
    k.x = fkey(xv.x * bv.x);
    k.y = fkey(xv.y * bv.y);
    k.z = fkey(xv.z * bv.z);
    k.w = fkey(xv.w * bv.w);
    return k;
}

// ============================ KERNEL A: compact ============================
// Pure streaming: read x row, filter >= FTHR, append packed candidates to
// global scratch. Tiny SMEM, one barrier. Near-pure DRAM read stream.
#define ATHREADS 512
#define ANIT     8               // NCOLS / (ATHREADS*4)

__global__ void __launch_bounds__(ATHREADS)
kcompact_kernel(const float* __restrict__ x) {
    __shared__ unsigned scnt;
    const int tid = threadIdx.x;
    const int row = blockIdx.x;
    if (tid == 0) scnt = 0;
    __syncthreads();

    const float4* xin = reinterpret_cast<const float4*>(x + (size_t)row * NCOLS);
    const float4* bfv = reinterpret_cast<const float4*>(g_boost);
    unsigned* gc = g_cand + (size_t)row * CAP;

    #pragma unroll
    for (int it = 0; it < ANIT; it++) {
        const int i4 = it * ATHREADS + tid;
        float4 xv = __ldcs(&xin[i4]);
        float4 bv = __ldg(&bfv[i4]);
        float v0 = xv.x * bv.x;
        float v1 = xv.y * bv.y;
        float v2 = xv.z * bv.z;
        float v3 = xv.w * bv.w;
        bool p0 = v0 >= FTHR, p1 = v1 >= FTHR, p2 = v2 >= FTHR, p3 = v3 >= FTHR;
        unsigned nc = (unsigned)p0 + (unsigned)p1 + (unsigned)p2 + (unsigned)p3;
        unsigned pos = atomicAdd(&scnt, nc);      // warp-aggregated by ptxas
        unsigned bi = (unsigned)i4 * 4u;
        if (p0) { if (pos < CAP) gc[pos] = (fkey_pos(v0) & 0xFFFFC000u) | (bi + 0u); pos++; }
        if (p1) { if (pos < CAP) gc[pos] = (fkey_pos(v1) & 0xFFFFC000u) | (bi + 1u); pos++; }
        if (p2) { if (pos < CAP) gc[pos] = (fkey_pos(v2) & 0xFFFFC000u) | (bi + 2u); pos++; }
        if (p3) { if (pos < CAP) gc[pos] = (fkey_pos(v3) & 0xFFFFC000u) | (bi + 3u); pos++; }
    }
    __syncthreads();
    if (tid == 0) g_count[row] = scnt;
}

// ============================ KERNEL B: select + emit ============================
#define BTHREADS 256
#define BNIT     16              // NCOLS / (BTHREADS*4)

// Parallel "find bin where cumulative count from the top reaches `need`".
// Outputs: bc[0]=bin, bc[1]=remaining needed within bin, bc[5]=bin count.
__device__ __forceinline__ void scan_sel(unsigned* hist, int nbins, unsigned need,
                                         unsigned* gsum, unsigned* bc) {
    const int tid = threadIdx.x;
    const int gsz = nbins >> 6;
    if (tid == 0) { bc[6] = 0u; bc[7] = 0u; }
    if (tid < 64) {
        unsigned s = 0;
        for (int i = 0; i < gsz; i++) s += hist[tid * gsz + i];
        gsum[tid] = s;
    }
    __syncthreads();
    unsigned suf = 0;
    if (tid < 64) {
        for (int j = tid; j < 64; j++) suf += gsum[j];
    }
    __syncthreads();
    if (tid < 64) {
        gsum[tid] = suf;                       // group suffix sums
        if (suf >= need) atomicMax(&bc[6], 0x10000u | (unsigned)tid);
    }
    __syncthreads();
    const unsigned g = bc[6] & 0xFFFFu;        // largest group with suffix >= need
    const unsigned cumAbove = (g == 63u) ? 0u : gsum[g + 1];
    __syncthreads();
    const unsigned need2 = need - cumAbove;
    if (tid < gsz) {
        unsigned s2 = 0;
        for (int j = (int)g * gsz + tid; j < ((int)g + 1) * gsz; j++) s2 += hist[j];
        gsum[tid] = s2;                        // within-group bin suffix sums
        if (s2 >= need2) atomicMax(&bc[7], 0x10000u | (unsigned)tid);
    }
    __syncthreads();
    if (tid == 0) {
        unsigned bl = bc[7] & 0xFFFFu;
        unsigned b = g * (unsigned)gsz + bl;
        unsigned cum2 = (bl == (unsigned)(gsz - 1)) ? 0u : gsum[bl + 1];
        bc[0] = b;
        bc[1] = need2 - cum2;
        bc[5] = hist[b];
    }
    __syncthreads();
}

__global__ void __launch_bounds__(BTHREADS, 8)
kselect_kernel(const float* __restrict__ x, float* __restrict__ out) {
    __shared__ unsigned hist[2048];
    __shared__ unsigned bmask[512];            // 16384 bits
    __shared__ unsigned bidx[BCAP];
    __shared__ unsigned bkey[BCAP];
    __shared__ unsigned gsum[64];
    __shared__ unsigned bc[8];
    __shared__ unsigned bcnt;
    __shared__ unsigned scnt;

    const int tid = threadIdx.x;
    const int row = blockIdx.x;
    const float*  xrow = x + (size_t)row * NCOLS;
    const float4* xin  = reinterpret_cast<const float4*>(xrow);
    const float4* bfv  = reinterpret_cast<const float4*>(g_boost);
    float4* out4 = reinterpret_cast<float4*>(out + (size_t)row * NCOLS);
    unsigned* gc = g_cand + (size_t)row * CAP;

    if (tid == 0) { bcnt = 0; }
    {
        const uint4 z = make_uint4(0, 0, 0, 0);
        reinterpret_cast<uint4*>(hist)[tid] = z;
        reinterpret_cast<uint4*>(hist)[tid + BTHREADS] = z;
        if (tid < 128) reinterpret_cast<uint4*>(bmask)[tid] = z;
    }
    __syncthreads();

    const unsigned total = g_count[row];

    bool fast = (total >= KSEL && total <= CAP);
    unsigned b1 = 0, rem1 = 0, Ecnt = 0;
    if (fast) {
        // ---- histogram over candidates (L2-resident) ----
        for (unsigned i = tid; i < total; i += BTHREADS)
            atomicAdd(&hist[min(2047u, (__ldg(&gc[i]) - KMIN) >> 15)], 1u);
        __syncthreads();
        scan_sel(hist, 2048, KSEL, gsum, bc);
        b1 = bc[0]; rem1 = bc[1]; Ecnt = bc[5];
        if (Ecnt > BCAP) fast = false;        // pathological: exact fallback below
    }

    if (fast) {
        // ---- classify: bin > b1 -> winner bit; bin == b1 -> boundary (+exact key) ----
        for (unsigned i = tid; i < total; i += BTHREADS) {
            unsigned c = __ldg(&gc[i]);
            unsigned bin = min(2047u, (c - KMIN) >> 15);   // idx bits don't reach bit 15
            if (bin > b1) {
                unsigned idx = c & 0x3FFFu;
                atomicOr(&bmask[idx >> 5], 1u << (idx & 31u));
            } else if (bin == b1) {
                unsigned idx = c & 0x3FFFu;
                unsigned p = atomicAdd(&bcnt, 1u);         // p < Ecnt <= BCAP
                bidx[p] = idx;
                bkey[p] = fkey(__ldg(&xrow[idx]) * __ldg(&g_boost[idx]));
            }
        }
        __syncthreads();

        // ---- boundary: rank (key desc, index asc) ----
        for (unsigned i = tid; i < Ecnt; i += BTHREADS) {
            unsigned mk = bkey[i], mi = bidx[i];
            unsigned rank = 0;
            for (unsigned j = 0; j < Ecnt; j++) {
                unsigned ok = bkey[j];
                rank += (ok > mk) || (ok == mk && bidx[j] < mi);
            }
            if (rank < rem1) atomicOr(&bmask[mi >> 5], 1u << (mi & 31u));
        }
        __syncthreads();

        // ---- single output pass from bitmask ----
        #pragma unroll
        for (int it = 0; it < BNIT; it++) {
            int i4 = it * BTHREADS + tid;
            unsigned w = bmask[i4 >> 3];
            unsigned f = (w >> ((i4 & 7) * 4)) & 0xFu;
            float4 o;
            o.x = (f & 1u) ? 1.0f : 0.0f;
            o.y = (f & 2u) ? 1.0f : 0.0f;
            o.z = (f & 4u) ? 1.0f : 0.0f;
            o.w = (f & 8u) ? 1.0f : 0.0f;
            __stcs(&out4[i4], o);
        }
    } else {
        // ================= FALLBACK: exact full 3-pass radix, recompute keys =================
        {
            const uint4 z = make_uint4(0, 0, 0, 0);
            reinterpret_cast<uint4*>(hist)[tid] = z;
            reinterpret_cast<uint4*>(hist)[tid + BTHREADS] = z;
        }
        __syncthreads();
        #pragma unroll
        for (int it = 0; it < BNIT; it++) {
            uint4 k = keys4_at(xin, bfv, it * BTHREADS + tid);
            atomicAdd(&hist[k.x >> 21], 1u);
            atomicAdd(&hist[k.y >> 21], 1u);
            atomicAdd(&hist[k.z >> 21], 1u);
            atomicAdd(&hist[k.w >> 21], 1u);
        }
        __syncthreads();
        scan_sel(hist, 2048, KSEL, gsum, bc);
        const unsigned fb1 = bc[0], frem1 = bc[1];
        {
            const uint4 z = make_uint4(0, 0, 0, 0);
            reinterpret_cast<uint4*>(hist)[tid] = z;
            reinterpret_cast<uint4*>(hist)[tid + BTHREADS] = z;
        }
        __syncthreads();
        #pragma unroll
        for (int it = 0; it < BNIT; it++) {
            uint4 k = keys4_at(xin, bfv, it * BTHREADS + tid);
            if ((k.x >> 21) == fb1) atomicAdd(&hist[(k.x >> 10) & 2047u], 1u);
            if ((k.y >> 21) == fb1) atomicAdd(&hist[(k.y >> 10) & 2047u], 1u);
            if ((k.z >> 21) == fb1) atomicAdd(&hist[(k.z >> 10) & 2047u], 1u);
            if ((k.w >> 21) == fb1) atomicAdd(&hist[(k.w >> 10) & 2047u], 1u);
        }
        __syncthreads();
        scan_sel(hist, 2048, frem1, gsum, bc);
        const unsigned fb2 = bc[0], frem2 = bc[1];
        const unsigned pref21 = (fb1 << 11) | fb2;
        reinterpret_cast<uint4*>(hist)[tid] = make_uint4(0, 0, 0, 0);
        __syncthreads();
        #pragma unroll
        for (int it = 0; it < BNIT; it++) {
            uint4 k = keys4_at(xin, bfv, it * BTHREADS + tid);
            if ((k.x >> 10) == pref21) atomicAdd(&hist[k.x & 1023u], 1u);
            if ((k.y >> 10) == pref21) atomicAdd(&hist[k.y & 1023u], 1u);
            if ((k.z >> 10) == pref21) atomicAdd(&hist[k.z & 1023u], 1u);
            if ((k.w >> 10) == pref21) atomicAdd(&hist[k.w & 1023u], 1u);
        }
        __syncthreads();
        scan_sel(hist, 1024, frem2, gsum, bc);
        const unsigned T    = (pref21 << 10) | bc[0];
        const unsigned rem3 = bc[1];
        const unsigned EcntF = bc[5];

        if (rem3 != EcntF) {
            if (tid == 0) scnt = 0;
            __syncthreads();
            #pragma unroll
            for (int it = 0; it < BNIT; it++) {
                int i4 = it * BTHREADS + tid;
                uint4 k = keys4_at(xin, bfv, i4);
                unsigned bi = (unsigned)i4 * 4u;
                if (k.x == T) { unsigned p = atomicAdd(&scnt, 1u); if (p < CAP) gc[p] = bi + 0u; }
                if (k.y == T) { unsigned p = atomicAdd(&scnt, 1u); if (p < CAP) gc[p] = bi + 1u; }
                if (k.z == T) { unsigned p = atomicAdd(&scnt, 1u); if (p < CAP) gc[p] = bi + 2u; }
                if (k.w == T) { unsigned p = atomicAdd(&scnt, 1u); if (p < CAP) gc[p] = bi + 3u; }
            }
            __syncthreads();
            if (tid == 0) {
                unsigned cnt = scnt; if (cnt > CAP) cnt = CAP;
                unsigned Ith = 0;
                for (unsigned r = 0; r < rem3; r++) {
                    unsigned best = 0xFFFFFFFFu, bj = 0;
                    for (unsigned j = 0; j < cnt; j++)
                        if (gc[j] < best) { best = gc[j]; bj = j; }
                    gc[bj] = 0xFFFFFFFFu;
                    Ith = best;
                }
                bc[3] = Ith;
            }
        } else if (tid == 0) {
            bc[3] = 0xFFFFFFFFu;
        }
        __syncthreads();
        const unsigned Ithr = bc[3];

        #pragma unroll
        for (int it = 0; it < BNIT; it++) {
            int i4 = it * BTHREADS + tid;
            uint4 k = keys4_at(xin, bfv, i4);
            unsigned bi = (unsigned)i4 * 4u;
            float4 o;
            o.x = (k.x > T || (k.x == T && bi + 0u <= Ithr)) ? 1.0f : 0.0f;
            o.y = (k.y > T || (k.y == T && bi + 1u <= Ithr)) ? 1.0f : 0.0f;
            o.z = (k.z > T || (k.z == T && bi + 2u <= Ithr)) ? 1.0f : 0.0f;
            o.w = (k.w > T || (k.w == T && bi + 3u <= Ithr)) ? 1.0f : 0.0f;
            out4[i4] = o;
        }
    }
}

extern "C" void kernel_launch(void* const* d_in, const int* in_sizes, int n_in,
                              void* d_out, int out_size) {
    const float* x    = (const float*)d_in[0];
    const float* duty = (const float*)d_in[1];
    float* out        = (float*)d_out;
    int rows = in_sizes[0] / NCOLS;
    if (rows > NROWS_MAX) rows = NROWS_MAX;

    boost_kernel<<<(NCOLS + 255) / 256, 256>>>(duty);
    kcompact_kernel<<<rows, ATHREADS>>>(x);
    kselect_kernel<<<rows, BTHREADS>>>(x, out);
}

// round 12
// speedup vs baseline: 1.4804x; 1.4804x over previous
#include <cuda_runtime.h>

#define NCOLS     16384
#define KSEL      655u
#define NTHREADS  512
#define NCHUNK    4              // chunks per row
#define CHUNKF4   1024           // float4 per chunk (4096 floats = 16KB)
#define CAP       2048u          // candidate buffer capacity
#define BCAP      512u           // boundary-bin buffer capacity

// shared layout (uint32 words)
#define OFF_STAGE  0                       // 2 buffers x 4096 words (32KB)
#define OFF_CAND   8192                    // CAP packed candidates
#define OFF_HIST   (OFF_CAND + CAP)        // 2048 bins
#define OFF_BMASK  (OFF_HIST + 2048)       // 512 words = 16384 bits
#define OFF_BIDX   (OFF_BMASK + 512)       // BCAP
#define OFF_BKEY   (OFF_BIDX + BCAP)       // BCAP
#define OFF_GSUM   (OFF_BKEY + BCAP)       // 64
#define OFF_BC     (OFF_GSUM + 64)         // 8
#define OFF_CNT    (OFF_BC + 8)            // word 13896
#define OFF_BCNT   (OFF_CNT + 1)           // word 13897
#define OFF_MBAR   (OFF_CNT + 4)           // word 13900: EVEN -> 8B aligned; 2 x u64
#define SMEM_UINTS (OFF_MBAR + 4)
#define SMEM_BYTES (SMEM_UINTS * 4)

// fkey(1.0f) = 0xBF800000 (low 15 bits zero: bin-aligned)
#define KMIN 0xBF800000u
#define FTHR 1.0f

__device__ float g_boost[NCOLS];

__global__ void boost_kernel(const float* __restrict__ duty) {
    int i = blockIdx.x * blockDim.x + threadIdx.x;
    if (i < NCOLS) {
        const float target = 655.0f / 16384.0f;   // exact in f32
        float d = target - duty[i];               // same f32 op as reference
        g_boost[i] = (float)exp((double)d);       // correctly-rounded f32 exp
    }
}

__device__ __forceinline__ unsigned fkey(float f) {
    unsigned u = __float_as_uint(f);
    return u ^ (((unsigned)((int)u >> 31)) | 0x80000000u);
}
__device__ __forceinline__ unsigned fkey_pos(float f) {
    return __float_as_uint(f) | 0x80000000u;
}

__device__ __forceinline__ uint4 keys4_at(const float4* __restrict__ xin,
                                          const float4* __restrict__ bfv, int i4) {
    float4 xv = __ldg(&xin[i4]);
    float4 bv = __ldg(&bfv[i4]);
    uint4 k;
    k.x = fkey(xv.x * bv.x);
    k.y = fkey(xv.y * bv.y);
    k.z = fkey(xv.z * bv.z);
    k.w = fkey(xv.w * bv.w);
    return k;
}

__device__ __forceinline__ unsigned smem_u32(const void* p) {
    unsigned a;
    asm("{ .reg .u64 t; cvta.to.shared.u64 t, %1; cvt.u32.u64 %0, t; }" : "=r"(a) : "l"(p));
    return a;
}

__device__ __forceinline__ void mbar_init(unsigned mbar, unsigned cnt) {
    asm volatile("mbarrier.init.shared.b64 [%0], %1;" :: "r"(mbar), "r"(cnt) : "memory");
}
__device__ __forceinline__ void mbar_expect_tx(unsigned mbar, unsigned bytes) {
    asm volatile("mbarrier.arrive.expect_tx.shared.b64 _, [%0], %1;" :: "r"(mbar), "r"(bytes) : "memory");
}
__device__ __forceinline__ void bulk_g2s(unsigned dst, const void* src, unsigned bytes, unsigned mbar) {
    asm volatile("cp.async.bulk.shared::cta.global.mbarrier::complete_tx::bytes [%0], [%1], %2, [%3];"
                 :: "r"(dst), "l"(src), "r"(bytes), "r"(mbar) : "memory");
}
__device__ __forceinline__ void mbar_wait(unsigned mbar, unsigned parity) {
    asm volatile(
        "{\n\t"
        ".reg .pred P;\n\t"
        "WAITLP_%=:\n\t"
        "mbarrier.try_wait.parity.acquire.cta.shared::cta.b64 P, [%0], %1, 0x989680;\n\t"
        "@P bra.uni WAITDN_%=;\n\t"
        "bra.uni WAITLP_%=;\n\t"
        "WAITDN_%=:\n\t"
        "}" :: "r"(mbar), "r"(parity) : "memory");
}

// Parallel "find bin where cumulative count from the top reaches `need`".
__device__ __forceinline__ void scan_sel(unsigned* hist, int nbins, unsigned need,
                                         unsigned* gsum, unsigned* bc) {
    const int tid = threadIdx.x;
    const int gsz = nbins >> 6;
    if (tid == 0) { bc[6] = 0u; bc[7] = 0u; }
    if (tid < 64) {
        unsigned s = 0;
        for (int i = 0; i < gsz; i++) s += hist[tid * gsz + i];
        gsum[tid] = s;
    }
    __syncthreads();
    unsigned suf = 0;
    if (tid < 64) {
        for (int j = tid; j < 64; j++) suf += gsum[j];
    }
    __syncthreads();
    if (tid < 64) {
        gsum[tid] = suf;
        if (suf >= need) atomicMax(&bc[6], 0x10000u | (unsigned)tid);
    }
    __syncthreads();
    const unsigned g = bc[6] & 0xFFFFu;
    const unsigned cumAbove = (g == 63u) ? 0u : gsum[g + 1];
    __syncthreads();
    const unsigned need2 = need - cumAbove;
    if (tid < gsz) {
        unsigned s2 = 0;
        for (int j = (int)g * gsz + tid; j < ((int)g + 1) * gsz; j++) s2 += hist[j];
        gsum[tid] = s2;
        if (s2 >= need2) atomicMax(&bc[7], 0x10000u | (unsigned)tid);
    }
    __syncthreads();
    if (tid == 0) {
        unsigned bl = bc[7] & 0xFFFFu;
        unsigned b = g * (unsigned)gsz + bl;
        unsigned cum2 = (bl == (unsigned)(gsz - 1)) ? 0u : gsum[bl + 1];
        bc[0] = b;
        bc[1] = need2 - cum2;
        bc[5] = hist[b];
    }
    __syncthreads();
}

__global__ void __launch_bounds__(NTHREADS, 4)
kwinners_kernel(const float* __restrict__ x, float* __restrict__ out) {
    extern __shared__ unsigned sh[];
    unsigned* cand  = sh + OFF_CAND;    // packed: (key & 0xFFFFC000) | idx14
    unsigned* hist  = sh + OFF_HIST;
    unsigned* bmask = sh + OFF_BMASK;
    unsigned* bidx  = sh + OFF_BIDX;
    unsigned* bkey  = sh + OFF_BKEY;
    unsigned* gsum  = sh + OFF_GSUM;
    unsigned* bc    = sh + OFF_BC;
    unsigned* scnt  = sh + OFF_CNT;
    unsigned* bcnt  = sh + OFF_BCNT;

    const int tid = threadIdx.x;
    const int row = blockIdx.x;
    const float*  xrow = x + (size_t)row * NCOLS;
    const float4* xin  = reinterpret_cast<const float4*>(xrow);
    const float4* bfv  = reinterpret_cast<const float4*>(g_boost);
    float4* out4 = reinterpret_cast<float4*>(out + (size_t)row * NCOLS);

    const unsigned stage_base = smem_u32(sh + OFF_STAGE);
    const unsigned mbar0 = smem_u32(sh + OFF_MBAR);
    const unsigned mbar1 = mbar0 + 8;

    if (tid == 0) {
        *scnt = 0; *bcnt = 0;
        mbar_init(mbar0, 1);
        mbar_init(mbar1, 1);
    }
    {
        const uint4 z = make_uint4(0, 0, 0, 0);
        reinterpret_cast<uint4*>(hist)[tid] = z;
        if (tid < 128) reinterpret_cast<uint4*>(bmask)[tid] = z;
    }
    __syncthreads();

    // kick off chunk 0 and 1 bulk copies
    if (tid == 0) {
        mbar_expect_tx(mbar0, 16384u);
        bulk_g2s(stage_base, xrow, 16384u, mbar0);
        mbar_expect_tx(mbar1, 16384u);
        bulk_g2s(stage_base + 16384u, xrow + CHUNKF4 * 4, 16384u, mbar1);
    }

    // ---- full-N pass from SMEM stage: compare, compact ----
    for (int c = 0; c < NCHUNK; c++) {
        mbar_wait((c & 1) ? mbar1 : mbar0, (unsigned)(c >> 1));
        const uint4* xs = reinterpret_cast<const uint4*>(sh + OFF_STAGE + (c & 1) * 4096);
        #pragma unroll
        for (int j = 0; j < 2; j++) {
            const int local = j * NTHREADS + tid;         // 0..1023
            const int i4 = c * CHUNKF4 + local;           // global float4 idx
            uint4 xw = xs[local];
            float4 bv = __ldg(&bfv[i4]);
            float v0 = __uint_as_float(xw.x) * bv.x;
            float v1 = __uint_as_float(xw.y) * bv.y;
            float v2 = __uint_as_float(xw.z) * bv.z;
            float v3 = __uint_as_float(xw.w) * bv.w;
            bool p0 = v0 >= FTHR, p1 = v1 >= FTHR, p2 = v2 >= FTHR, p3 = v3 >= FTHR;
            unsigned nc = (unsigned)p0 + (unsigned)p1 + (unsigned)p2 + (unsigned)p3;
            unsigned pos = atomicAdd(scnt, nc);           // warp-aggregated
            unsigned bi = (unsigned)i4 * 4u;
            if (p0) { if (pos < CAP) cand[pos] = (fkey_pos(v0) & 0xFFFFC000u) | (bi + 0u); pos++; }
            if (p1) { if (pos < CAP) cand[pos] = (fkey_pos(v1) & 0xFFFFC000u) | (bi + 1u); pos++; }
            if (p2) { if (pos < CAP) cand[pos] = (fkey_pos(v2) & 0xFFFFC000u) | (bi + 2u); pos++; }
            if (p3) { if (pos < CAP) cand[pos] = (fkey_pos(v3) & 0xFFFFC000u) | (bi + 3u); pos++; }
        }
        __syncthreads();                                  // everyone done with this buffer
        if (tid == 0 && c + 2 < NCHUNK) {
            unsigned mb = (c & 1) ? mbar1 : mbar0;
            mbar_expect_tx(mb, 16384u);
            bulk_g2s(stage_base + (unsigned)(c & 1) * 16384u,
                     xrow + (size_t)(c + 2) * CHUNKF4 * 4, 16384u, mb);
        }
    }
    __syncthreads();
    const unsigned total = *scnt;

    bool fast = (total >= KSEL && total <= CAP);
    unsigned b1 = 0, rem1 = 0, Ecnt = 0;
    if (fast) {
        // ---- deferred histogram over candidates ----
        for (unsigned i = tid; i < total; i += NTHREADS)
            atomicAdd(&hist[min(2047u, (cand[i] - KMIN) >> 15)], 1u);
        __syncthreads();
        scan_sel(hist, 2048, KSEL, gsum, bc);
        b1 = bc[0]; rem1 = bc[1]; Ecnt = bc[5];
        if (Ecnt > BCAP) fast = false;
    }

    if (fast) {
        // ---- classify: bin > b1 -> winner bit; bin == b1 -> boundary (+exact key) ----
        for (unsigned i = tid; i < total; i += NTHREADS) {
            unsigned c = cand[i];
            unsigned bin = min(2047u, (c - KMIN) >> 15);
            if (bin > b1) {
                unsigned idx = c & 0x3FFFu;
                atomicOr(&bmask[idx >> 5], 1u << (idx & 31u));
            } else if (bin == b1) {
                unsigned idx = c & 0x3FFFu;
                unsigned p = atomicAdd(bcnt, 1u);          // p < Ecnt <= BCAP
                bidx[p] = idx;
                bkey[p] = fkey(__ldg(&xrow[idx]) * __ldg(&g_boost[idx]));
            }
        }
        __syncthreads();

        // ---- boundary: rank (key desc, index asc) ----
        for (unsigned i = tid; i < Ecnt; i += NTHREADS) {
            unsigned mk = bkey[i], mi = bidx[i];
            unsigned rank = 0;
            for (unsigned j = 0; j < Ecnt; j++) {
                unsigned ok = bkey[j];
                rank += (ok > mk) || (ok == mk && bidx[j] < mi);
            }
            if (rank < rem1) atomicOr(&bmask[mi >> 5], 1u << (mi & 31u));
        }
        __syncthreads();

        // ---- single output pass from bitmask ----
        #pragma unroll
        for (int it = 0; it < 8; it++) {
            int i4 = it * NTHREADS + tid;
            unsigned w = bmask[i4 >> 3];
            unsigned f = (w >> ((i4 & 7) * 4)) & 0xFu;
            float4 o;
            o.x = (f & 1u) ? 1.0f : 0.0f;
            o.y = (f & 2u) ? 1.0f : 0.0f;
            o.z = (f & 4u) ? 1.0f : 0.0f;
            o.w = (f & 8u) ? 1.0f : 0.0f;
            __stcs(&out4[i4], o);
        }
    } else {
        // ================= FALLBACK: exact full 3-pass radix from global =================
        reinterpret_cast<uint4*>(hist)[tid] = make_uint4(0, 0, 0, 0);
        __syncthreads();
        #pragma unroll
        for (int it = 0; it < 8; it++) {
            uint4 k = keys4_at(xin, bfv, it * NTHREADS + tid);
            atomicAdd(&hist[k.x >> 21], 1u);
            atomicAdd(&hist[k.y >> 21], 1u);
            atomicAdd(&hist[k.z >> 21], 1u);
            atomicAdd(&hist[k.w >> 21], 1u);
        }
        __syncthreads();
        scan_sel(hist, 2048, KSEL, gsum, bc);
        const unsigned fb1 = bc[0], frem1 = bc[1];
        reinterpret_cast<uint4*>(hist)[tid] = make_uint4(0, 0, 0, 0);
        __syncthreads();
        #pragma unroll
        for (int it = 0; it < 8; it++) {
            uint4 k = keys4_at(xin, bfv, it * NTHREADS + tid);
            if ((k.x >> 21) == fb1) atomicAdd(&hist[(k.x >> 10) & 2047u], 1u);
            if ((k.y >> 21) == fb1) atomicAdd(&hist[(k.y >> 10) & 2047u], 1u);
            if ((k.z >> 21) == fb1) atomicAdd(&hist[(k.z >> 10) & 2047u], 1u);
            if ((k.w >> 21) == fb1) atomicAdd(&hist[(k.w >> 10) & 2047u], 1u);
        }
        __syncthreads();
        scan_sel(hist, 2048, frem1, gsum, bc);
        const unsigned fb2 = bc[0], frem2 = bc[1];
        const unsigned pref21 = (fb1 << 11) | fb2;
        if (tid < 256) reinterpret_cast<uint4*>(hist)[tid] = make_uint4(0, 0, 0, 0);
        __syncthreads();
        #pragma unroll
        for (int it = 0; it < 8; it++) {
            uint4 k = keys4_at(xin, bfv, it * NTHREADS + tid);
            if ((k.x >> 10) == pref21) atomicAdd(&hist[k.x & 1023u], 1u);
            if ((k.y >> 10) == pref21) atomicAdd(&hist[k.y & 1023u], 1u);
            if ((k.z >> 10) == pref21) atomicAdd(&hist[k.z & 1023u], 1u);
            if ((k.w >> 10) == pref21) atomicAdd(&hist[k.w & 1023u], 1u);
        }
        __syncthreads();
        scan_sel(hist, 1024, frem2, gsum, bc);
        const unsigned T    = (pref21 << 10) | bc[0];
        const unsigned rem3 = bc[1];
        const unsigned EcntF = bc[5];

        if (rem3 != EcntF) {
            if (tid == 0) *scnt = 0;
            __syncthreads();
            #pragma unroll
            for (int it = 0; it < 8; it++) {
                int i4 = it * NTHREADS + tid;
                uint4 k = keys4_at(xin, bfv, i4);
                unsigned bi = (unsigned)i4 * 4u;
                if (k.x == T) { unsigned p = atomicAdd(scnt, 1u); if (p < CAP) cand[p] = bi + 0u; }
                if (k.y == T) { unsigned p = atomicAdd(scnt, 1u); if (p < CAP) cand[p] = bi + 1u; }
                if (k.z == T) { unsigned p = atomicAdd(scnt, 1u); if (p < CAP) cand[p] = bi + 2u; }
                if (k.w == T) { unsigned p = atomicAdd(scnt, 1u); if (p < CAP) cand[p] = bi + 3u; }
            }
            __syncthreads();
            if (tid == 0) {
                unsigned cnt = *scnt; if (cnt > CAP) cnt = CAP;
                unsigned Ith = 0;
                for (unsigned r = 0; r < rem3; r++) {
                    unsigned best = 0xFFFFFFFFu, bj = 0;
                    for (unsigned j = 0; j < cnt; j++)
                        if (cand[j] < best) { best = cand[j]; bj = j; }
                    cand[bj] = 0xFFFFFFFFu;
                    Ith = best;
                }
                bc[3] = Ith;
            }
        } else if (tid == 0) {
            bc[3] = 0xFFFFFFFFu;
        }
        __syncthreads();
        const unsigned Ithr = bc[3];

        #pragma unroll
        for (int it = 0; it < 8; it++) {
            int i4 = it * NTHREADS + tid;
            uint4 k = keys4_at(xin, bfv, i4);
            unsigned bi = (unsigned)i4 * 4u;
            float4 o;
            o.x = (k.x > T || (k.x == T && bi + 0u <= Ithr)) ? 1.0f : 0.0f;
            o.y = (k.y > T || (k.y == T && bi + 1u <= Ithr)) ? 1.0f : 0.0f;
            o.z = (k.z > T || (k.z == T && bi + 2u <= Ithr)) ? 1.0f : 0.0f;
            o.w = (k.w > T || (k.w == T && bi + 3u <= Ithr)) ? 1.0f : 0.0f;
            out4[i4] = o;
        }
    }
}

extern "C" void kernel_launch(void* const* d_in, const int* in_sizes, int n_in,
                              void* d_out, int out_size) {
    const float* x    = (const float*)d_in[0];
    const float* duty = (const float*)d_in[1];
    float* out        = (float*)d_out;
    int rows = in_sizes[0] / NCOLS;

    cudaFuncSetAttribute(kwinners_kernel,
                         cudaFuncAttributeMaxDynamicSharedMemorySize, SMEM_BYTES);

    boost_kernel<<<(NCOLS + 255) / 256, 256>>>(duty);
    kwinners_kernel<<<rows, NTHREADS, SMEM_BYTES>>>(x, out);
}